// round 10
// baseline (speedup 1.0000x reference)
#include <cuda_runtime.h>
#include <cuda_bf16.h>

#define N_    4096
#define FIN_  500
#define H_    64
#define C_    7
#define E_    65536
#define B_    1024
#define A_    20
#define NW_   128          // bitset words per row
#define CH_   (C_*H_)      // 448
#define HB_   65536        // 16-bit histogram bins
#define CAP_  2048
#define KSEL_ (E_/2)
#define KB_   50
#define NSTG_ (FIN_/KB_)   // 10
#define NTILE_ (N_/16)     // 256 encoder tiles
#define EB_   64           // k_edges grid

// ---------------- scratch (device globals; zero at module load) -------------
__device__ float    g_embed[N_*H_];
__device__ unsigned g_adj[N_*NW_];
__device__ int      g_cls[N_];
__device__ float    g_thresh;
__device__ int      g_hist[HB_];
__device__ unsigned g_cand[CAP_];
__device__ int      g_ncand;
__device__ unsigned g_barcnt;
__device__ unsigned g_bargen;

// ---------------- packed f32x2 helpers --------------------------------------
__device__ __forceinline__ unsigned long long pack2(float lo, float hi) {
    unsigned long long v;
    asm("mov.b64 %0, {%1, %2};" : "=l"(v) : "f"(lo), "f"(hi));
    return v;
}
__device__ __forceinline__ void unpack2(unsigned long long v, float& lo, float& hi) {
    asm("mov.b64 {%0, %1}, %2;" : "=f"(lo), "=f"(hi) : "l"(v));
}
__device__ __forceinline__ void fma2(unsigned long long& d,
                                     unsigned long long a, unsigned long long b) {
    asm("fma.rn.f32x2 %0, %1, %2, %0;" : "+l"(d) : "l"(a), "l"(b));
}

// ---------------- grid-wide barrier (all blocks resident by construction) ----
__device__ __forceinline__ void gridbar(unsigned& gen, int nb) {
    __syncthreads();
    if (threadIdx.x == 0) {
        __threadfence();
        if (atomicAdd(&g_barcnt, 1u) == (unsigned)nb - 1u) {
            g_barcnt = 0u;
            __threadfence();
            *(volatile unsigned*)&g_bargen = gen + 1u;
        } else {
            while (*(volatile unsigned*)&g_bargen == gen) __nanosleep(64);
        }
    }
    __syncthreads();
    __threadfence();
    gen += 1u;
}

// ================= 1) edges: hist -> pick -> adj, one launch =================
__global__ __launch_bounds__(256) void k_edges(
        const int* __restrict__ ei, const float* __restrict__ ew) {
    __shared__ int s_scan[256];
    __shared__ unsigned s_cand[CAP_];
    __shared__ int s_bucket, s_krem;
    __shared__ float s_thresh;
    int tid = threadIdx.x, bid = blockIdx.x;
    unsigned gen = *(volatile unsigned*)&g_bargen;
    int g = bid*256 + tid;                 // 16384 threads total

    // ---- P1: histogram (float4) + zero adj + reset candidate counter -------
    {
        float4 wv = ((const float4*)ew)[g];
        atomicAdd(&g_hist[__float_as_uint(wv.x) >> 16], 1);
        atomicAdd(&g_hist[__float_as_uint(wv.y) >> 16], 1);
        atomicAdd(&g_hist[__float_as_uint(wv.z) >> 16], 1);
        atomicAdd(&g_hist[__float_as_uint(wv.w) >> 16], 1);
        uint4 z = make_uint4(0u, 0u, 0u, 0u);
#pragma unroll
        for (int j = 0; j < 8; j++)
            ((uint4*)g_adj)[g + j*16384] = z;
        if (g == 0) g_ncand = 0;
    }
    gridbar(gen, EB_);

    // ---- P2: per-block redundant scan -> bucket/krem; gather candidates -----
    {
        const int CHK = HB_/256;           // 256 bins/thread
        int abase = HB_ - (tid + 1)*CHK;
        int psum = 0;
        const int4* hp = (const int4*)(g_hist + abase);
#pragma unroll 16
        for (int i = 0; i < CHK/4; i++) {
            int4 h4 = hp[i];
            psum += h4.x + h4.y + h4.z + h4.w;
        }
        s_scan[tid] = psum;
        __syncthreads();
        for (int off = 1; off < 256; off <<= 1) {
            int v = (tid >= off) ? s_scan[tid - off] : 0;
            __syncthreads();
            s_scan[tid] += v;
            __syncthreads();
        }
        int incl = s_scan[tid], excl = incl - psum;
        if (excl < KSEL_ && incl >= KSEL_) {
            int cum = excl;
            int dbase = HB_ - 1 - tid*CHK;
            for (int i = 0; i < CHK; i++) {
                int b = dbase - i, h = g_hist[b];
                cum += h;
                if (cum >= KSEL_) { s_bucket = b; s_krem = KSEL_ - (cum - h); break; }
            }
        }
        __syncthreads();
        int bucket = s_bucket;
        uint4 k4 = ((const uint4*)ew)[g];  // block's contiguous chunk
        unsigned kk;
        kk = k4.x; if ((int)(kk >> 16) == bucket) { int p = atomicAdd(&g_ncand, 1); if (p < CAP_) g_cand[p] = kk; }
        kk = k4.y; if ((int)(kk >> 16) == bucket) { int p = atomicAdd(&g_ncand, 1); if (p < CAP_) g_cand[p] = kk; }
        kk = k4.z; if ((int)(kk >> 16) == bucket) { int p = atomicAdd(&g_ncand, 1); if (p < CAP_) g_cand[p] = kk; }
        kk = k4.w; if ((int)(kk >> 16) == bucket) { int p = atomicAdd(&g_ncand, 1); if (p < CAP_) g_cand[p] = kk; }
    }
    gridbar(gen, EB_);

    // ---- P3: redundant exact selection -> thresh; adj build; hist rezero ----
    {
        int nc = g_ncand; if (nc > CAP_) nc = CAP_;
        for (int i = tid; i < nc; i += 256) s_cand[i] = g_cand[i];
        __syncthreads();
        int krem = s_krem;
        for (int i = tid; i < nc; i += 256) {
            unsigned v = s_cand[i];
            int gt = 0, eq = 0;
            for (int j = 0; j < nc; j++) {
                unsigned u = s_cand[j];
                gt += (u > v); eq += (u == v);
            }
            if (gt < krem && krem <= gt + eq) s_thresh = __uint_as_float(v);
        }
        __syncthreads();
        float th = s_thresh;
        if (g == 0) g_thresh = th;
        for (int i = g; i < E_ + N_; i += EB_*256) {
            if (i < E_) {
                if (ew[i] >= th) {
                    int s = ei[i], d = ei[E_ + i];
                    atomicOr(&g_adj[s*NW_ + (d >> 5)], 1u << (d & 31));
                }
            } else {
                int n = i - E_;
                atomicOr(&g_adj[n*NW_ + (n >> 5)], 1u << (n & 31));   // diag
            }
        }
        ((int4*)g_hist)[g] = make_int4(0, 0, 0, 0);   // 16384 int4 = HB_ ints
    }
}

// ================= 2) encoder + cls, one launch ===============================
struct EncSm { float xs[2][16][KB_]; float ws[2][KB_][64]; };
struct ClsSm { float sa[C_][64]; float sa2[C_]; float swp[CH_]; float sbp[C_]; };
union  ECSm  { EncSm enc; ClsSm cls; };

__global__ __launch_bounds__(256, 2) void k_enc_cls(
        const float* __restrict__ x, const float* __restrict__ Wenc,
        const float* __restrict__ benc, const int* __restrict__ aidx,
        const float* __restrict__ Wpred, const float* __restrict__ bpred,
        float* __restrict__ out, int nb) {
    __shared__ ECSm sm;
    int tid = threadIdx.x, bid = blockIdx.x;
    unsigned gen = *(volatile unsigned*)&g_bargen;
    int row = tid & 15;
    int c0  = (tid >> 4) * 4;

    // loop-invariant load/store offsets (i = tid + j*256; i<800)
    // xs flat store offset == i; x global delta = i + (i/50)*450
    int xd[4], wso[4];
    bool act3 = (tid < 32);
#pragma unroll
    for (int j = 0; j < 4; j++) {
        int i = tid + j*256;
        xd[j]  = i + (i/KB_)*(FIN_ - KB_);
        wso[j] = (i >> 4)*16 + (i & 15);       // float4 units in [50][16]
    }
    const float4* Wenc4 = (const float4*)Wenc;

    for (int t = bid; t < NTILE_; t += nb) {
        int r0 = t * 16;
        const float* xb = x + r0*FIN_;
        unsigned long long acc0 = 0ull, acc1 = 0ull;
        float xr[4]; float4 wr[4];
        float* xsf0 = (float*)sm.enc.xs[0];
        float* xsf1 = (float*)sm.enc.xs[1];
        float4* wsf0 = (float4*)sm.enc.ws[0];
        float4* wsf1 = (float4*)sm.enc.ws[1];

        {   // prologue: stage 0
            xr[0] = xb[xd[0]]; xr[1] = xb[xd[1]]; xr[2] = xb[xd[2]];
            wr[0] = Wenc4[wso[0]]; wr[1] = Wenc4[wso[1]]; wr[2] = Wenc4[wso[2]];
            if (act3) { xr[3] = xb[xd[3] ]; wr[3] = Wenc4[wso[3]]; }
            xsf0[tid] = xr[0]; xsf0[tid+256] = xr[1]; xsf0[tid+512] = xr[2];
            wsf0[wso[0]] = wr[0]; wsf0[wso[1]] = wr[1]; wsf0[wso[2]] = wr[2];
            if (act3) { xsf0[tid+768] = xr[3]; wsf0[wso[3]] = wr[3]; }
        }
        __syncthreads();

        for (int s = 0; s < NSTG_; s++) {
            int buf = s & 1;
            if (s + 1 < NSTG_) {
                int k0 = (s + 1) * KB_;
                int wk = k0 * 16;
                xr[0] = xb[k0 + xd[0]]; xr[1] = xb[k0 + xd[1]]; xr[2] = xb[k0 + xd[2]];
                wr[0] = Wenc4[wk + wso[0]]; wr[1] = Wenc4[wk + wso[1]]; wr[2] = Wenc4[wk + wso[2]];
                if (act3) { xr[3] = xb[k0 + xd[3]]; wr[3] = Wenc4[wk + wso[3]]; }
            }
            {
                const float* xsr = &sm.enc.xs[buf][row][0];
                const float (*wsr)[64] = sm.enc.ws[buf];
#pragma unroll 5
                for (int kk2 = 0; kk2 < KB_/2; kk2++) {
                    float2 ap = *(const float2*)&xsr[2*kk2];
                    unsigned long long aa0 = pack2(ap.x, ap.x);
                    unsigned long long aa1 = pack2(ap.y, ap.y);
                    float4 b0 = *(const float4*)&wsr[2*kk2][c0];
                    float4 b1 = *(const float4*)&wsr[2*kk2 + 1][c0];
                    fma2(acc0, aa0, pack2(b0.x, b0.y));
                    fma2(acc1, aa0, pack2(b0.z, b0.w));
                    fma2(acc0, aa1, pack2(b1.x, b1.y));
                    fma2(acc1, aa1, pack2(b1.z, b1.w));
                }
            }
            if (s + 1 < NSTG_) {
                float* xsn = (s & 1) ? xsf0 : xsf1;
                float4* wsn = (s & 1) ? wsf0 : wsf1;
                xsn[tid] = xr[0]; xsn[tid+256] = xr[1]; xsn[tid+512] = xr[2];
                wsn[wso[0]] = wr[0]; wsn[wso[1]] = wr[1]; wsn[wso[2]] = wr[2];
                if (act3) { xsn[tid+768] = xr[3]; wsn[wso[3]] = wr[3]; }
            }
            __syncthreads();
        }
        float v0, v1, v2, v3;
        unpack2(acc0, v0, v1); unpack2(acc1, v2, v3);
        v0 += benc[c0];   v1 += benc[c0+1];
        v2 += benc[c0+2]; v3 += benc[c0+3];
        *(float4*)&g_embed[(r0 + row)*H_ + c0] =
            make_float4(fmaxf(v0,0.f), fmaxf(v1,0.f), fmaxf(v2,0.f), fmaxf(v3,0.f));
        __syncthreads();
    }
    gridbar(gen, nb);

    // ---- cls phase: anchors (per-block, redundant) + assign + log_softmax ---
    if (tid < 64) {
        for (int c = 0; c < C_; c++) {
            float s = 0.f;
#pragma unroll 4
            for (int a = 0; a < A_; a++)
                s += g_embed[aidx[c*A_ + a]*H_ + tid];
            sm.cls.sa[c][tid] = s * (1.f / A_);
        }
    } else {
        for (int i = tid - 64; i < CH_; i += 192) sm.cls.swp[i] = Wpred[i];
        if (tid - 64 < C_) sm.cls.sbp[tid - 64] = bpred[tid - 64];
    }
    __syncthreads();
    if (tid < C_) {
        float s = 0.f;
        for (int h = 0; h < H_; h++) { float v = sm.cls.sa[tid][h]; s += v*v; }
        sm.cls.sa2[tid] = s;
    }
    __syncthreads();

    for (int base = bid*16; base < N_; base += nb*16) {
        if (tid < 16) {
            int n = base + tid;
            float dot[C_], xo[C_];
            float en2 = 0.f;
#pragma unroll
            for (int c = 0; c < C_; c++) { dot[c] = 0.f; xo[c] = sm.cls.sbp[c]; }
            const float4* ep = (const float4*)(g_embed + n*H_);
#pragma unroll
            for (int i = 0; i < 16; i++) {
                float4 e4 = ep[i];
                en2 += e4.x*e4.x + e4.y*e4.y + e4.z*e4.z + e4.w*e4.w;
#pragma unroll
                for (int c = 0; c < C_; c++) {
                    dot[c] += e4.x*sm.cls.sa[c][4*i]   + e4.y*sm.cls.sa[c][4*i+1]
                            + e4.z*sm.cls.sa[c][4*i+2] + e4.w*sm.cls.sa[c][4*i+3];
                    xo[c]  += e4.x*sm.cls.swp[(4*i)*C_ + c]   + e4.y*sm.cls.swp[(4*i+1)*C_ + c]
                            + e4.z*sm.cls.swp[(4*i+2)*C_ + c] + e4.w*sm.cls.swp[(4*i+3)*C_ + c];
                }
            }
            int best = 0; float bd = 3.4e38f;
#pragma unroll
            for (int c = 0; c < C_; c++) {
                float d2 = en2 - 2.f*dot[c] + sm.cls.sa2[c];
                if (d2 < bd) { bd = d2; best = c; }
            }
            g_cls[n] = best;
            float m = xo[0];
#pragma unroll
            for (int c = 1; c < C_; c++) m = fmaxf(m, xo[c]);
            float se = 0.f;
#pragma unroll
            for (int c = 0; c < C_; c++) se += expf(xo[c] - m);
            float ls = logf(se);
#pragma unroll
            for (int c = 0; c < C_; c++) out[2*B_ + n*C_ + c] = xo[c] - m - ls;
        }
    }
}

// ================= 3) fused 2-hop + class-mean + decoder =====================
#define L1CAP_ 512
#define L2CAP_ 1536
__device__ __forceinline__ void barg(int t) {
    asm volatile("bar.sync %0, 128;" :: "r"(t + 1) : "memory");
}
__global__ __launch_bounds__(384) void k_cmean_dec(
        const int* __restrict__ ego, const int* __restrict__ pos,
        const int* __restrict__ neg,
        const float* __restrict__ W1, const float* __restrict__ b1,
        const float* __restrict__ W2, const float* __restrict__ b2,
        float* __restrict__ out) {
    __shared__ unsigned hop[3][NW_];
    __shared__ int   list1[3][L1CAP_];
    __shared__ int   list[3][L2CAP_];
    __shared__ float sums[3][CH_];
    __shared__ int   cnt[3][C_];
    __shared__ int   n1[3], nlist[3];
    __shared__ float op[CH_], on[CH_];
    __shared__ float part[8][32];

    int b = blockIdx.x;
    int tid = threadIdx.x;
    int t   = tid >> 7;
    int gt  = tid & 127;
    int gw  = gt >> 5;
    int lane = tid & 31;

    int v = (t == 0) ? ego[b] : (t == 1) ? pos[b] : neg[b];
    for (int i = gt; i < CH_; i += 128) sums[t][i] = 0.f;
    if (gt < C_) cnt[t][gt] = 0;
    if (gt == 0) { n1[t] = 0; nlist[t] = 0; }
    hop[t][gt] = g_adj[v*NW_ + gt];
    barg(t);

    {
        unsigned bits = hop[t][gt];
        while (bits) {
            int bb = __ffs(bits) - 1; bits &= bits - 1;
            int p = atomicAdd(&n1[t], 1);
            if (p < L1CAP_) list1[t][p] = gt*32 + bb;
        }
    }
    barg(t);
    int m1 = n1[t]; if (m1 > L1CAP_) m1 = L1CAP_;

    for (int j = gw; j < m1; j += 4) {
        const uint4* rp = (const uint4*)&g_adj[list1[t][j]*NW_];
        uint4 r4 = rp[lane];
        if (r4.x) atomicOr(&hop[t][lane*4 + 0], r4.x);
        if (r4.y) atomicOr(&hop[t][lane*4 + 1], r4.y);
        if (r4.z) atomicOr(&hop[t][lane*4 + 2], r4.z);
        if (r4.w) atomicOr(&hop[t][lane*4 + 3], r4.w);
    }
    barg(t);

    {
        unsigned bits = hop[t][gt];
        while (bits) {
            int bb = __ffs(bits) - 1; bits &= bits - 1;
            int node = gt*32 + bb;
            int p = atomicAdd(&nlist[t], 1);
            if (p < L2CAP_) list[t][p] = node | (g_cls[node] << 12);
        }
    }
    barg(t);

    int M = nlist[t]; if (M > L2CAP_) M = L2CAP_;
    for (int li = gw; li < M; li += 4) {
        int e = list[t][li];
        int n = e & 0xFFF, c = e >> 12;
        float2 e2 = *(const float2*)&g_embed[n*H_ + lane*2];
        atomicAdd(&sums[t][c*H_ + lane*2],     e2.x);
        atomicAdd(&sums[t][c*H_ + lane*2 + 1], e2.y);
        if (lane == 0) atomicAdd(&cnt[t][c], 1);
    }
    __syncthreads();

    for (int i = tid; i < CH_; i += 384) {
        int c = i >> 6;
        float ce = (float)max(cnt[0][c], 1);
        float cp = (float)max(cnt[1][c], 1);
        float cn = (float)max(cnt[2][c], 1);
        float e  = sums[0][i] / ce;
        float p  = sums[1][i] / cp;
        float nn = sums[2][i] / cn;
        float dp = e - p, dn = e - nn;
        op[i] = dp*dp;
        on[i] = dn*dn;
    }
    __syncthreads();

    int warp = tid >> 5;
    if (warp < 8) {
        const float* o = (warp < 4) ? op : on;
        int i0 = (warp & 3) * 112;
        float h = 0.f;
        for (int i = i0; i < i0 + 112; i++)
            h += o[i] * W1[i*32 + lane];
        part[warp][lane] = h;
    }
    __syncthreads();
    if (warp == 0 || warp == 4) {
        int pb = warp;
        float hv = part[pb][lane] + part[pb+1][lane]
                 + part[pb+2][lane] + part[pb+3][lane] + b1[lane];
        hv = fmaxf(hv, 0.f);
        float vv = hv * W2[lane];
#pragma unroll
        for (int o2 = 16; o2 > 0; o2 >>= 1)
            vv += __shfl_down_sync(0xffffffffu, vv, o2);
        if (lane == 0) out[(warp == 0) ? b : (B_ + b)] = vv + b2[0];
    }
}

// ================= fallback kernels (no grid barrier) =========================
__global__ __launch_bounds__(256, 2) void k_encoder_f(
        const float* __restrict__ x, const float* __restrict__ Wenc,
        const float* __restrict__ benc) {
    __shared__ float xs[16][KB_];
    __shared__ float ws[KB_][64];
    int tid = threadIdx.x, row = tid & 15, c0 = (tid >> 4)*4;
    int r0 = blockIdx.x * 16;
    unsigned long long acc0 = 0ull, acc1 = 0ull;
    for (int k0 = 0; k0 < FIN_; k0 += KB_) {
        for (int i = tid; i < 800; i += 256) {
            ((float*)xs)[i] = x[(r0 + i/KB_)*FIN_ + k0 + i%KB_];
            ((float4*)ws)[(i>>4)*16 + (i&15)] =
                *(const float4*)&Wenc[(k0 + (i>>4))*H_ + (i&15)*4];
        }
        __syncthreads();
#pragma unroll 5
        for (int kk2 = 0; kk2 < KB_/2; kk2++) {
            float2 ap = *(const float2*)&xs[row][2*kk2];
            unsigned long long aa0 = pack2(ap.x, ap.x);
            unsigned long long aa1 = pack2(ap.y, ap.y);
            float4 b0 = *(const float4*)&ws[2*kk2][c0];
            float4 b1 = *(const float4*)&ws[2*kk2 + 1][c0];
            fma2(acc0, aa0, pack2(b0.x, b0.y));
            fma2(acc1, aa0, pack2(b0.z, b0.w));
            fma2(acc0, aa1, pack2(b1.x, b1.y));
            fma2(acc1, aa1, pack2(b1.z, b1.w));
        }
        __syncthreads();
    }
    float v0, v1, v2, v3;
    unpack2(acc0, v0, v1); unpack2(acc1, v2, v3);
    v0 += benc[c0];   v1 += benc[c0+1];
    v2 += benc[c0+2]; v3 += benc[c0+3];
    *(float4*)&g_embed[(r0 + row)*H_ + c0] =
        make_float4(fmaxf(v0,0.f), fmaxf(v1,0.f), fmaxf(v2,0.f), fmaxf(v3,0.f));
}
__global__ void k_cls_f(const int* __restrict__ aidx, const float* __restrict__ Wpred,
                        const float* __restrict__ bpred, float* __restrict__ out) {
    __shared__ float sa[C_][64]; __shared__ float sa2[C_];
    __shared__ float swp[CH_]; __shared__ float sbp[C_];
    int tid = threadIdx.x;
    if (tid < 64) {
        for (int c = 0; c < C_; c++) {
            float s = 0.f;
#pragma unroll 5
            for (int a = 0; a < A_; a++) s += g_embed[aidx[c*A_ + a]*H_ + tid];
            sa[c][tid] = s * (1.f / A_);
        }
    } else {
        for (int i = tid - 64; i < CH_; i += 64) swp[i] = Wpred[i];
        if (tid - 64 < C_) sbp[tid - 64] = bpred[tid - 64];
    }
    __syncthreads();
    if (tid < C_) {
        float s = 0.f;
        for (int h = 0; h < H_; h++) { float v = sa[tid][h]; s += v*v; }
        sa2[tid] = s;
    }
    __syncthreads();
    int n = blockIdx.x * 128 + tid;
    float dot[C_], xo[C_]; float en2 = 0.f;
#pragma unroll
    for (int c = 0; c < C_; c++) { dot[c] = 0.f; xo[c] = sbp[c]; }
    const float4* ep = (const float4*)(g_embed + n*H_);
#pragma unroll
    for (int i = 0; i < 16; i++) {
        float4 e4 = ep[i];
        en2 += e4.x*e4.x + e4.y*e4.y + e4.z*e4.z + e4.w*e4.w;
#pragma unroll
        for (int c = 0; c < C_; c++) {
            dot[c] += e4.x*sa[c][4*i] + e4.y*sa[c][4*i+1]
                    + e4.z*sa[c][4*i+2] + e4.w*sa[c][4*i+3];
            xo[c]  += e4.x*swp[(4*i)*C_ + c] + e4.y*swp[(4*i+1)*C_ + c]
                    + e4.z*swp[(4*i+2)*C_ + c] + e4.w*swp[(4*i+3)*C_ + c];
        }
    }
    int best = 0; float bd = 3.4e38f;
#pragma unroll
    for (int c = 0; c < C_; c++) {
        float d2 = en2 - 2.f*dot[c] + sa2[c];
        if (d2 < bd) { bd = d2; best = c; }
    }
    g_cls[n] = best;
    float m = xo[0];
#pragma unroll
    for (int c = 1; c < C_; c++) m = fmaxf(m, xo[c]);
    float se = 0.f;
#pragma unroll
    for (int c = 0; c < C_; c++) se += expf(xo[c] - m);
    float ls = logf(se);
#pragma unroll
    for (int c = 0; c < C_; c++) out[2*B_ + n*C_ + c] = xo[c] - m - ls;
}

// ---------------- host config (static init; no device allocation) -----------
struct ECfg {
    int nb = 0;
    ECfg() {
        int sms = 0, bpm = 0;
        if (cudaDeviceGetAttribute(&sms, cudaDevAttrMultiProcessorCount, 0) != cudaSuccess) return;
        if (cudaOccupancyMaxActiveBlocksPerMultiprocessor(&bpm, k_enc_cls, 256, 0) != cudaSuccess) return;
        long t = (long)sms * bpm;
        if (t > NTILE_) t = NTILE_;
        if (t >= EB_ && sms >= EB_) nb = (int)t;
    }
};
static ECfg cfg;

// ---------------- launch ------------------------------------------------------
extern "C" void kernel_launch(void* const* d_in, const int* in_sizes, int n_in,
                              void* d_out, int out_size) {
    const float* x    = (const float*)d_in[0];
    const int*   ei   = (const int*)  d_in[1];
    const int*   ego  = (const int*)  d_in[2];
    const int*   pos  = (const int*)  d_in[3];
    const int*   neg  = (const int*)  d_in[4];
    const float* ew   = (const float*)d_in[5];
    const int*   aidx = (const int*)  d_in[6];
    int wb = (in_sizes[7] == FIN_*H_) ? 7 : 8;
    const float* Wenc  = (const float*)d_in[wb + 0];
    const float* benc  = (const float*)d_in[wb + 1];
    const float* Wpred = (const float*)d_in[wb + 2];
    const float* bpred = (const float*)d_in[wb + 3];
    const float* W1    = (const float*)d_in[wb + 4];
    const float* b1    = (const float*)d_in[wb + 5];
    const float* W2    = (const float*)d_in[wb + 6];
    const float* b2    = (const float*)d_in[wb + 7];
    float* out = (float*)d_out;

    k_edges<<<EB_, 256>>>(ei, ew);
    if (cfg.nb > 0) {
        k_enc_cls<<<cfg.nb, 256>>>(x, Wenc, benc, aidx, Wpred, bpred, out, cfg.nb);
    } else {
        k_encoder_f<<<NTILE_, 256>>>(x, Wenc, benc);
        k_cls_f    <<<N_/128, 128>>>(aidx, Wpred, bpred, out);
    }
    k_cmean_dec<<<B_, 384>>>(ego, pos, neg, W1, b1, W2, b2, out);
}

// round 11
// speedup vs baseline: 1.2248x; 1.2248x over previous
#include <cuda_runtime.h>
#include <cuda_bf16.h>

#define N_    4096
#define FIN_  500
#define H_    64
#define C_    7
#define E_    65536
#define B_    1024
#define A_    20
#define NW_   128          // bitset words per row
#define CH_   (C_*H_)      // 448
#define HB_   65536        // 16-bit histogram bins
#define CAP_  2048
#define KSEL_ (E_/2)
#define KB_   50
#define NSTG_ (FIN_/KB_)   // 10

// ---------------- scratch (device globals; zero at module load) -------------
__device__ float    g_embed[N_*H_];
__device__ unsigned g_adj[N_*NW_];
__device__ int      g_cls[N_];
__device__ float    g_thresh;
__device__ int      g_hist[HB_];

// ---------------- packed f32x2 helpers --------------------------------------
__device__ __forceinline__ unsigned long long pack2(float lo, float hi) {
    unsigned long long v;
    asm("mov.b64 %0, {%1, %2};" : "=l"(v) : "f"(lo), "f"(hi));
    return v;
}
__device__ __forceinline__ void unpack2(unsigned long long v, float& lo, float& hi) {
    asm("mov.b64 {%0, %1}, %2;" : "=f"(lo), "=f"(hi) : "l"(v));
}
__device__ __forceinline__ void fma2(unsigned long long& d,
                                     unsigned long long a, unsigned long long b) {
    asm("fma.rn.f32x2 %0, %1, %2, %0;" : "+l"(d) : "l"(a), "l"(b));
}

// ---------------- 1a) histogram (float4) + zero g_adj -----------------------
__global__ void k_hist(const float* __restrict__ w) {
    int i = blockIdx.x * blockDim.x + threadIdx.x;     // 16384 threads
    float4 wv = ((const float4*)w)[i];
    atomicAdd(&g_hist[__float_as_uint(wv.x) >> 16], 1);
    atomicAdd(&g_hist[__float_as_uint(wv.y) >> 16], 1);
    atomicAdd(&g_hist[__float_as_uint(wv.z) >> 16], 1);
    atomicAdd(&g_hist[__float_as_uint(wv.w) >> 16], 1);
    uint4 z = make_uint4(0u, 0u, 0u, 0u);
#pragma unroll
    for (int j = 0; j < 8; j++)
        ((uint4*)g_adj)[i + j*16384] = z;              // 131072 uint4 total
}

// ---------------- 1b) exact k-th largest (vectorized scans) -----------------
__global__ void k_pick(const float* __restrict__ w, int k) {
    __shared__ int s_scan[1024];
    __shared__ unsigned s_cand[CAP_];
    __shared__ int s_n, s_bucket, s_krem;
    int tid = threadIdx.x;
    const int CHK = 64;
    int abase = HB_ - (tid + 1) * CHK;

    int psum = 0;
    const int4* hp = (const int4*)(g_hist + abase);
#pragma unroll
    for (int i = 0; i < 16; i++) {
        int4 h4 = hp[i];
        psum += h4.x + h4.y + h4.z + h4.w;
    }
    s_scan[tid] = psum;
    __syncthreads();
    for (int off = 1; off < 1024; off <<= 1) {
        int v = (tid >= off) ? s_scan[tid - off] : 0;
        __syncthreads();
        s_scan[tid] += v;
        __syncthreads();
    }
    int incl = s_scan[tid];
    int excl = incl - psum;
    if (excl < k && incl >= k) {
        int cum = excl;
        int dbase = HB_ - 1 - tid * CHK;
        for (int i = 0; i < CHK; i++) {
            int b = dbase - i;
            int h = g_hist[b];
            cum += h;
            if (cum >= k) { s_bucket = b; s_krem = k - (cum - h); break; }
        }
    }
    if (tid == 0) s_n = 0;
    __syncthreads();
    int4 z4 = make_int4(0, 0, 0, 0);
#pragma unroll
    for (int i = 0; i < 16; i++) ((int4*)(g_hist + abase))[i] = z4;

    int bucket = s_bucket;
    const uint4* wp = (const uint4*)w;
#pragma unroll 4
    for (int i = tid; i < E_/4; i += 1024) {
        uint4 k4 = wp[i];
        unsigned kk;
        kk = k4.x; if ((int)(kk >> 16) == bucket) { int p = atomicAdd(&s_n, 1); if (p < CAP_) s_cand[p] = kk; }
        kk = k4.y; if ((int)(kk >> 16) == bucket) { int p = atomicAdd(&s_n, 1); if (p < CAP_) s_cand[p] = kk; }
        kk = k4.z; if ((int)(kk >> 16) == bucket) { int p = atomicAdd(&s_n, 1); if (p < CAP_) s_cand[p] = kk; }
        kk = k4.w; if ((int)(kk >> 16) == bucket) { int p = atomicAdd(&s_n, 1); if (p < CAP_) s_cand[p] = kk; }
    }
    __syncthreads();
    int n = s_n < CAP_ ? s_n : CAP_;
    int krem = s_krem;
    for (int i = tid; i < n; i += 1024) {
        unsigned v = s_cand[i];
        int gt = 0, eq = 0;
        for (int j = 0; j < n; j++) {
            unsigned u = s_cand[j];
            gt += (u > v); eq += (u == v);
        }
        if (gt < krem && krem <= gt + eq)
            g_thresh = __uint_as_float(v);
    }
}

// ---------------- 2) encoder: 16x64 tiles, 4 independent FFMA2 chains -------
// Per stage per thread: 25 kk2 iterations; even/odd kk go to separate
// accumulators -> 4 chains of depth 25 (was 2 of depth 50) for 2x ILP.
__global__ __launch_bounds__(256, 2) void k_encoder(
        const float* __restrict__ x,
        const float* __restrict__ Wenc,
        const float* __restrict__ benc) {
    __shared__ __align__(16) float xs[2][16][KB_];   // [buf][row][kk]
    __shared__ __align__(16) float ws[2][KB_][64];
    int tid = threadIdx.x;
    int row = tid & 15;
    int c0  = (tid >> 4) * 4;
    int r0  = blockIdx.x * 16;

    unsigned long long acc0a = 0ull, acc0b = 0ull;
    unsigned long long acc1a = 0ull, acc1b = 0ull;
    float xr[4]; float4 wr[4];

    {   // prologue: stage 0 (x: 800 scalars, w: 800 float4)
#pragma unroll
        for (int j = 0; j < 4; j++) {
            int i = tid + j*256;
            if (i < 800) {
                xr[j] = x[(r0 + i/KB_)*FIN_ + (i % KB_)];
                wr[j] = *(const float4*)&Wenc[(i >> 4)*H_ + (i & 15)*4];
            }
        }
#pragma unroll
        for (int j = 0; j < 4; j++) {
            int i = tid + j*256;
            if (i < 800) {
                xs[0][i / KB_][i % KB_] = xr[j];
                *(float4*)&ws[0][i >> 4][(i & 15)*4] = wr[j];
            }
        }
    }
    __syncthreads();

    for (int s = 0; s < NSTG_; s++) {
        int buf = s & 1;
        if (s + 1 < NSTG_) {
            int k0 = (s + 1) * KB_;
#pragma unroll
            for (int j = 0; j < 4; j++) {
                int i = tid + j*256;
                if (i < 800) {
                    xr[j] = x[(r0 + i/KB_)*FIN_ + k0 + (i % KB_)];
                    wr[j] = *(const float4*)&Wenc[(k0 + (i >> 4))*H_ + (i & 15)*4];
                }
            }
        }
#pragma unroll 5
        for (int kk2 = 0; kk2 < KB_/2; kk2++) {
            float2 ap = *(const float2*)&xs[buf][row][2*kk2];
            unsigned long long aa0 = pack2(ap.x, ap.x);
            unsigned long long aa1 = pack2(ap.y, ap.y);
            float4 b0 = *(const float4*)&ws[buf][2*kk2][c0];
            float4 b1 = *(const float4*)&ws[buf][2*kk2 + 1][c0];
            fma2(acc0a, aa0, pack2(b0.x, b0.y));
            fma2(acc1a, aa0, pack2(b0.z, b0.w));
            fma2(acc0b, aa1, pack2(b1.x, b1.y));
            fma2(acc1b, aa1, pack2(b1.z, b1.w));
        }
        if (s + 1 < NSTG_) {
            int nb = buf ^ 1;
#pragma unroll
            for (int j = 0; j < 4; j++) {
                int i = tid + j*256;
                if (i < 800) {
                    xs[nb][i / KB_][i % KB_] = xr[j];
                    *(float4*)&ws[nb][i >> 4][(i & 15)*4] = wr[j];
                }
            }
        }
        __syncthreads();
    }
    float v0a, v1a, v0b, v1b, v2a, v3a, v2b, v3b;
    unpack2(acc0a, v0a, v1a); unpack2(acc0b, v0b, v1b);
    unpack2(acc1a, v2a, v3a); unpack2(acc1b, v2b, v3b);
    float v0 = v0a + v0b + benc[c0];
    float v1 = v1a + v1b + benc[c0+1];
    float v2 = v2a + v2b + benc[c0+2];
    float v3 = v3a + v3b + benc[c0+3];
    *(float4*)&g_embed[(r0 + row)*H_ + c0] =
        make_float4(fmaxf(v0,0.f), fmaxf(v1,0.f), fmaxf(v2,0.f), fmaxf(v3,0.f));
}

// ---------------- 3) adjacency bitset ---------------------------------------
__global__ void k_adj(const int* __restrict__ ei, const float* __restrict__ ew) {
    int i = blockIdx.x * blockDim.x + threadIdx.x;
    float th = g_thresh;
    if (i < E_) {
        if (ew[i] >= th) {
            int s = ei[i], d = ei[E_ + i];
            atomicOr(&g_adj[s*NW_ + (d >> 5)], 1u << (d & 31));
        }
    } else if (i < E_ + N_) {
        int n = i - E_;
        atomicOr(&g_adj[n*NW_ + (n >> 5)], 1u << (n & 31));   // diag
    }
}

// ---------------- 4) anchors (in-block) + class assign + log_softmax --------
__global__ void k_cls(const int* __restrict__ aidx,
                      const float* __restrict__ Wpred,
                      const float* __restrict__ bpred,
                      float* __restrict__ out) {
    __shared__ float sa[C_][64];
    __shared__ float sa2[C_];
    __shared__ float swp[64*C_];
    __shared__ float sbp[C_];
    int tid = threadIdx.x;           // 128
    if (tid < 64) {
        for (int c = 0; c < C_; c++) {
            float s = 0.f;
#pragma unroll 5
            for (int a = 0; a < A_; a++)
                s += g_embed[aidx[c*A_ + a]*64 + tid];
            sa[c][tid] = s * (1.f / A_);
        }
    } else {
        for (int i = tid - 64; i < 64*C_; i += 64) swp[i] = Wpred[i];
        if (tid - 64 < C_) sbp[tid - 64] = bpred[tid - 64];
    }
    __syncthreads();
    if (tid < C_) {
        float s = 0.f;
        for (int h = 0; h < 64; h++) { float v = sa[tid][h]; s += v*v; }
        sa2[tid] = s;
    }
    __syncthreads();

    int n = blockIdx.x * 128 + tid;
    float e[64];
    const float4* ep = (const float4*)(g_embed + n*64);
#pragma unroll
    for (int i = 0; i < 16; i++) {
        float4 v = ep[i];
        e[4*i] = v.x; e[4*i+1] = v.y; e[4*i+2] = v.z; e[4*i+3] = v.w;
    }
    float en2 = 0.f;
#pragma unroll
    for (int h = 0; h < 64; h++) en2 += e[h]*e[h];
    int best = 0; float bd = 3.4e38f;
    for (int c = 0; c < C_; c++) {
        float dot = 0.f;
#pragma unroll
        for (int h = 0; h < 64; h++) dot += e[h] * sa[c][h];
        float d2 = en2 - 2.f*dot + sa2[c];
        if (d2 < bd) { bd = d2; best = c; }
    }
    g_cls[n] = best;
    float xo[C_];
    for (int c = 0; c < C_; c++) {
        float s = sbp[c];
#pragma unroll
        for (int h = 0; h < 64; h++) s += e[h] * swp[h*C_ + c];
        xo[c] = s;
    }
    float m = xo[0];
    for (int c = 1; c < C_; c++) m = fmaxf(m, xo[c]);
    float se = 0.f;
    for (int c = 0; c < C_; c++) se += expf(xo[c] - m);
    float ls = logf(se);
    for (int c = 0; c < C_; c++) out[2*B_ + n*C_ + c] = xo[c] - m - ls;
}

// ---------------- 5) fused 2-hop + class-mean + decoder, 3 queries parallel --
#define L1CAP_ 512
#define L2CAP_ 1536
__device__ __forceinline__ void barg(int t) {
    asm volatile("bar.sync %0, 128;" :: "r"(t + 1) : "memory");
}
__global__ __launch_bounds__(384) void k_cmean_dec(
        const int* __restrict__ ego, const int* __restrict__ pos,
        const int* __restrict__ neg,
        const float* __restrict__ W1, const float* __restrict__ b1,
        const float* __restrict__ W2, const float* __restrict__ b2,
        float* __restrict__ out) {
    __shared__ unsigned hop[3][NW_];
    __shared__ int   list1[3][L1CAP_];
    __shared__ int   list[3][L2CAP_];     // node | (cls<<12)
    __shared__ float sums[3][CH_];
    __shared__ int   cnt[3][C_];
    __shared__ int   n1[3], nlist[3];
    __shared__ float op[CH_], on[CH_];
    __shared__ float part[8][32];

    int b = blockIdx.x;
    int tid = threadIdx.x;            // 384
    int t   = tid >> 7;               // query group 0..2
    int gt  = tid & 127;              // id within group
    int gw  = gt >> 5;                // warp within group 0..3
    int lane = tid & 31;

    int v = (t == 0) ? ego[b] : (t == 1) ? pos[b] : neg[b];
    for (int i = gt; i < CH_; i += 128) sums[t][i] = 0.f;
    if (gt < C_) cnt[t][gt] = 0;
    if (gt == 0) { n1[t] = 0; nlist[t] = 0; }
    hop[t][gt] = g_adj[v*NW_ + gt];
    barg(t);

    {
        unsigned bits = hop[t][gt];
        while (bits) {
            int bb = __ffs(bits) - 1; bits &= bits - 1;
            int p = atomicAdd(&n1[t], 1);
            if (p < L1CAP_) list1[t][p] = gt*32 + bb;
        }
    }
    barg(t);
    int m1 = n1[t]; if (m1 > L1CAP_) m1 = L1CAP_;

    for (int j = gw; j < m1; j += 4) {
        const uint4* rp = (const uint4*)&g_adj[list1[t][j]*NW_];
        uint4 r4 = rp[lane];
        if (r4.x) atomicOr(&hop[t][lane*4 + 0], r4.x);
        if (r4.y) atomicOr(&hop[t][lane*4 + 1], r4.y);
        if (r4.z) atomicOr(&hop[t][lane*4 + 2], r4.z);
        if (r4.w) atomicOr(&hop[t][lane*4 + 3], r4.w);
    }
    barg(t);

    {
        unsigned bits = hop[t][gt];
        while (bits) {
            int bb = __ffs(bits) - 1; bits &= bits - 1;
            int node = gt*32 + bb;
            int p = atomicAdd(&nlist[t], 1);
            if (p < L2CAP_) list[t][p] = node | (g_cls[node] << 12);
        }
    }
    barg(t);

    int M = nlist[t]; if (M > L2CAP_) M = L2CAP_;
    for (int li = gw; li < M; li += 4) {
        int e = list[t][li];
        int n = e & 0xFFF, c = e >> 12;
        float2 e2 = *(const float2*)&g_embed[n*H_ + lane*2];
        atomicAdd(&sums[t][c*H_ + lane*2],     e2.x);
        atomicAdd(&sums[t][c*H_ + lane*2 + 1], e2.y);
        if (lane == 0) atomicAdd(&cnt[t][c], 1);
    }
    __syncthreads();   // all three groups done

    for (int i = tid; i < CH_; i += 384) {
        int c = i >> 6;
        float ce = (float)max(cnt[0][c], 1);
        float cp = (float)max(cnt[1][c], 1);
        float cn = (float)max(cnt[2][c], 1);
        float e  = sums[0][i] / ce;
        float p  = sums[1][i] / cp;
        float nn = sums[2][i] / cn;
        float dp = e - p, dn = e - nn;
        op[i] = dp*dp;
        on[i] = dn*dn;
    }
    __syncthreads();

    int warp = tid >> 5;
    if (warp < 8) {
        const float* o = (warp < 4) ? op : on;
        int i0 = (warp & 3) * 112;
        float h = 0.f;
        for (int i = i0; i < i0 + 112; i++)
            h += o[i] * W1[i*32 + lane];
        part[warp][lane] = h;
    }
    __syncthreads();
    if (warp == 0 || warp == 4) {
        int pb = warp;
        float hv = part[pb][lane] + part[pb+1][lane]
                 + part[pb+2][lane] + part[pb+3][lane] + b1[lane];
        hv = fmaxf(hv, 0.f);
        float vv = hv * W2[lane];
#pragma unroll
        for (int o2 = 16; o2 > 0; o2 >>= 1)
            vv += __shfl_down_sync(0xffffffffu, vv, o2);
        if (lane == 0) out[(warp == 0) ? b : (B_ + b)] = vv + b2[0];
    }
}

// ---------------- stream fork resources (host-side, created at load) --------
struct HxStreams {
    cudaStream_t s2 = nullptr;
    cudaEvent_t  fork = nullptr, join = nullptr;
    bool ok = false;
    HxStreams() {
        if (cudaStreamCreateWithFlags(&s2, cudaStreamNonBlocking) != cudaSuccess) return;
        if (cudaEventCreateWithFlags(&fork, cudaEventDisableTiming) != cudaSuccess) return;
        if (cudaEventCreateWithFlags(&join, cudaEventDisableTiming) != cudaSuccess) return;
        ok = true;
    }
};
static HxStreams hx;

// ---------------- launch ------------------------------------------------------
extern "C" void kernel_launch(void* const* d_in, const int* in_sizes, int n_in,
                              void* d_out, int out_size) {
    const float* x    = (const float*)d_in[0];
    const int*   ei   = (const int*)  d_in[1];
    const int*   ego  = (const int*)  d_in[2];
    const int*   pos  = (const int*)  d_in[3];
    const int*   neg  = (const int*)  d_in[4];
    const float* ew   = (const float*)d_in[5];
    const int*   aidx = (const int*)  d_in[6];
    int wb = (in_sizes[7] == FIN_*H_) ? 7 : 8;
    const float* Wenc  = (const float*)d_in[wb + 0];
    const float* benc  = (const float*)d_in[wb + 1];
    const float* Wpred = (const float*)d_in[wb + 2];
    const float* bpred = (const float*)d_in[wb + 3];
    const float* W1    = (const float*)d_in[wb + 4];
    const float* b1    = (const float*)d_in[wb + 5];
    const float* W2    = (const float*)d_in[wb + 6];
    const float* b2    = (const float*)d_in[wb + 7];
    float* out = (float*)d_out;

    if (hx.ok) {
        cudaEventRecord(hx.fork, 0);
        cudaStreamWaitEvent(hx.s2, hx.fork, 0);

        k_hist <<<64, 256>>>(ew);
        k_pick <<<1, 1024>>>(ew, KSEL_);
        k_adj  <<<(E_ + N_ + 255)/256, 256>>>(ei, ew);

        k_encoder<<<N_/16, 256, 0, hx.s2>>>(x, Wenc, benc);
        k_cls    <<<N_/128, 128, 0, hx.s2>>>(aidx, Wpred, bpred, out);
        cudaEventRecord(hx.join, hx.s2);
        cudaStreamWaitEvent(0, hx.join, 0);

        k_cmean_dec<<<B_, 384>>>(ego, pos, neg, W1, b1, W2, b2, out);
    } else {
        k_hist   <<<64, 256>>>(ew);
        k_pick   <<<1, 1024>>>(ew, KSEL_);
        k_encoder<<<N_/16, 256>>>(x, Wenc, benc);
        k_adj    <<<(E_ + N_ + 255)/256, 256>>>(ei, ew);
        k_cls    <<<N_/128, 128>>>(aidx, Wpred, bpred, out);
        k_cmean_dec<<<B_, 384>>>(ego, pos, neg, W1, b1, W2, b2, out);
    }
}